// round 4
// baseline (speedup 1.0000x reference)
#include <cuda_runtime.h>
#include <stdint.h>

#define NQ      8
#define NPAIRS  28
#define NB      16384
#define THREADS 128

typedef unsigned long long u64;

// batch-shared precomputed constants
__device__ float2 g_vqc_cs[2 * NQ];   // cos/sin(theta_w/2) per (layer,qubit)
__device__ float  g_hw[3][NQ];        // 0.5*phi_w(l0), 0.5*omega_w(l0), 0.5*phi_w(l1)

__global__ void precompute_vqc(const float* __restrict__ w) {
    int i = threadIdx.x;
    if (i < 2 * NQ) {
        float th = w[i * 3 + 1];
        float c, s;
        __sincosf(0.5f * th, &s, &c);
        g_vqc_cs[i] = make_float2(c, s);
    }
    if (i < NQ) {
        g_hw[0][i] = 0.5f * w[i * 3 + 0];
        g_hw[1][i] = 0.5f * w[i * 3 + 2];
        g_hw[2][i] = 0.5f * w[(NQ + i) * 3 + 0];
    }
}

// ---------------- f32x2 packed helpers ----------------
__device__ __forceinline__ u64 pk(float lo, float hi) {
    u64 v; asm("mov.b64 %0, {%1, %2};" : "=l"(v) : "f"(lo), "f"(hi)); return v;
}
__device__ __forceinline__ void upk(u64 v, float& lo, float& hi) {
    asm("mov.b64 {%0, %1}, %2;" : "=f"(lo), "=f"(hi) : "l"(v));
}
__device__ __forceinline__ u64 bc2(float x) { return pk(x, x); }
__device__ __forceinline__ u64 fma2(u64 a, u64 b, u64 c) {
    u64 d; asm("fma.rn.f32x2 %0, %1, %2, %3;" : "=l"(d) : "l"(a), "l"(b), "l"(c)); return d;
}
__device__ __forceinline__ u64 mul2(u64 a, u64 b) {
    u64 d; asm("mul.rn.f32x2 %0, %1, %2;" : "=l"(d) : "l"(a), "l"(b)); return d;
}
__device__ __forceinline__ u64 shflx2(u64 v, int m) {
    float lo, hi; upk(v, lo, hi);
    lo = __shfl_xor_sync(0xffffffffu, lo, m);
    hi = __shfl_xor_sync(0xffffffffu, hi, m);
    return pk(lo, hi);
}

// ---------------- gate primitives ----------------
// State: s = lane*8 + r. Qubit k -> state bit 7-k.
// Lane bits 4..0 hold qubits 0..4 (until relabeled), reg bits qubits 5..7.

// RY on a lane-slot qubit: xor-mask may be multi-bit (relabeled), sign from lam.
__device__ __forceinline__ void ry_lane_m(u64 (&a)[8], float c, float s,
                                          int mask, unsigned lam) {
    const u64 c2 = bc2(c);
    const u64 sg2 = bc2(lam ? s : -s);
#pragma unroll
    for (int r = 0; r < 8; r++) {
        u64 p = shflx2(a[r], mask);
        a[r] = fma2(sg2, p, mul2(c2, a[r]));
    }
}

// RY on a reg-slot qubit (reg bit mask m in {4,2,1})
__device__ __forceinline__ void ry_reg_m(u64 (&a)[8], float c, float s, int m) {
    const u64 c2 = bc2(c), s2 = bc2(s), ns2 = bc2(-s);
#pragma unroll
    for (int r = 0; r < 8; r++) {
        if (!(r & m)) {
            u64 x = a[r], y = a[r | m];
            a[r]     = fma2(ns2, y, mul2(c2, x));
            a[r | m] = fma2(s2,  x, mul2(c2, y));
        }
    }
}

// Diagonal phase gate; lane-part sign sum passed in as 'base', reg part WHT'd.
__device__ __forceinline__ void diag_gate_base(u64 (&a)[8], float base,
                                               float h5, float h6, float h7) {
    float w0[8] = { base, -h7, -h6, 0.f, -h5, 0.f, 0.f, 0.f };
#pragma unroll
    for (int st = 1; st < 8; st <<= 1) {
#pragma unroll
        for (int i = 0; i < 8; i++) {
            if (!(i & st)) {
                float u = w0[i], v = w0[i | st];
                w0[i] = u + v; w0[i | st] = u - v;
            }
        }
    }
#pragma unroll
    for (int r = 0; r < 8; r++) {
        float phr = w0[r];
        float q = rintf(phr * 0.15915494309189535f);
        phr = fmaf(q, -6.2831855f, phr);
        float cc, ss;
        __sincosf(phr, &ss, &cc);
        float x, y; upk(a[r], x, y);
        a[r] = pk(fmaf(cc, x, -ss * y), fmaf(cc, y, ss * x));
    }
}

__device__ __forceinline__ float lane_wht(float v, unsigned lane) {
#pragma unroll
    for (int m = 1; m < 32; m <<= 1) {
        float t = __shfl_xor_sync(0xffffffffu, v, m);
        v = (lane & m) ? (t - v) : (v + t);
    }
    return v;
}

// ---------------- main kernel ----------------

__global__ void __launch_bounds__(THREADS)
vqc_kernel(const float* __restrict__ theta, const float* __restrict__ phi,
           const float* __restrict__ jup, const float* __restrict__ w,
           float* __restrict__ out) {
    const unsigned tid  = blockIdx.x * THREADS + threadIdx.x;
    const unsigned b    = tid >> 5;
    const unsigned lane = tid & 31;

    float ph[NQ];
    float cq[NQ], sq[NQ];   // cos/sin(theta/4)
    float ch[NQ], sh[NQ];   // cos/sin(theta/2) via double-angle
#pragma unroll
    for (int k = 0; k < NQ; k++) {
        float th = theta[b * NQ + k];
        ph[k] = phi[b * NQ + k];
        __sincosf(0.25f * th, &sq[k], &cq[k]);
        sh[k] = 2.f * sq[k] * cq[k];
        ch[k] = fmaf(-2.f * sq[k], sq[k], 1.f);
    }

    // ===== Ising Walsh table over reg bits (lane part in index 0) =====
    float exr[8];
    {
        const float HP = 1.5707963267948966f;
        float il = 0.f, U0 = 0.f, U1 = 0.f, U2 = 0.f;
        float J56 = 0.f, J57 = 0.f, J67 = 0.f;
        int p = 0;
#pragma unroll
        for (int i = 0; i < 8; i++) {
#pragma unroll
            for (int j = i + 1; j < 8; j++) {
                float J = jup[(size_t)b * NPAIRS + p];
                if (j < 5) {
                    int d = ((lane >> (4 - i)) ^ (lane >> (4 - j))) & 1;
                    il += d ? J : -J;
                } else if (i < 5) {
                    int bi = (lane >> (4 - i)) & 1;
                    float v = bi ? J : -J;
                    if (j == 5) U0 += v; else if (j == 6) U1 += v; else U2 += v;
                } else {
                    if (i == 5 && j == 6) J56 = J;
                    else if (i == 5 && j == 7) J57 = J;
                    else J67 = J;
                }
                p++;
            }
        }
        exr[0] = il * HP;  exr[1] = U2 * HP;   exr[2] = U1 * HP;  exr[3] = -J67 * HP;
        exr[4] = U0 * HP;  exr[5] = -J57 * HP; exr[6] = -J56 * HP; exr[7] = 0.f;
    }

    // ===== Fused: product state after encoding RY + DIAG1 phase =====
    u64 a[8];
    {
        float hc[8];
#pragma unroll
        for (int k = 0; k < NQ; k++) hc[k] = fmaf(0.5f, ph[k], g_hw[0][k]);
        float base = 0.f;
#pragma unroll
        for (int k = 0; k < 5; k++)
            base += ((lane >> (4 - k)) & 1) ? hc[k] : -hc[k];
        float w0[8];
        w0[0] = base + exr[0]; w0[1] = exr[1] - hc[7]; w0[2] = exr[2] - hc[6]; w0[3] = exr[3];
        w0[4] = exr[4] - hc[5]; w0[5] = exr[5]; w0[6] = exr[6]; w0[7] = exr[7];
#pragma unroll
        for (int st = 1; st < 8; st <<= 1) {
#pragma unroll
            for (int i = 0; i < 8; i++) {
                if (!(i & st)) {
                    float u = w0[i], v = w0[i | st];
                    w0[i] = u + v; w0[i | st] = u - v;
                }
            }
        }
        float lf = 1.f;
#pragma unroll
        for (int k = 0; k < 5; k++)
            lf *= ((lane >> (4 - k)) & 1) ? sh[k] : ch[k];
        float f56[4];
        f56[0] = ch[5] * ch[6]; f56[1] = ch[5] * sh[6];
        f56[2] = sh[5] * ch[6]; f56[3] = sh[5] * sh[6];
#pragma unroll
        for (int r = 0; r < 8; r++) {
            float v = lf * f56[r >> 1] * ((r & 1) ? sh[7] : ch[7]);
            float phr = w0[r];
            float q = rintf(phr * 0.15915494309189535f);
            phr = fmaf(q, -6.2831855f, phr);
            float cc, ss;
            __sincosf(phr, &ss, &cc);
            a[r] = pk(v * cc, v * ss);
        }
    }

    // ===== layer 0 Rot-RY (identity mapping: masks 16,8,4,2,1) =====
    {
        float c[8], s[8];
#pragma unroll
        for (int k = 0; k < NQ; k++) { float2 cs = g_vqc_cs[k]; c[k] = cs.x; s[k] = cs.y; }
        ry_lane_m(a, c[0], s[0], 16, (lane >> 4) & 1u);
        ry_lane_m(a, c[1], s[1],  8, (lane >> 3) & 1u);
        ry_lane_m(a, c[2], s[2],  4, (lane >> 2) & 1u);
        ry_lane_m(a, c[3], s[3],  2, (lane >> 1) & 1u);
        ry_lane_m(a, c[4], s[4],  1,  lane       & 1u);
        ry_reg_m(a, c[5], s[5], 4);
        ry_reg_m(a, c[6], s[6], 2);
        ry_reg_m(a, c[7], s[7], 1);
    }
    // DIAG2: layer0 Rot-RZ(omega)
    {
        float hc[8];
#pragma unroll
        for (int k = 0; k < NQ; k++) hc[k] = g_hw[1][k];
        float base = 0.f;
#pragma unroll
        for (int k = 0; k < 5; k++)
            base += ((lane >> (4 - k)) & 1) ? hc[k] : -hc[k];
        diag_gate_base(a, base, hc[5], hc[6], hc[7]);
    }

    // ===== CNOT ring 1 =====
    // (0,1)(1,2)(2,3)(3,4) folded into lane relabeling: logical bit j at
    // physical lane p is the suffix parity Lam_j = p_j ^ ... ^ p_4.
    // Flipping logical bit j <=> physical xor masks X = {1,3,6,12,24}.
    const unsigned lam4 = (lane >> 4) & 1u;
    const unsigned lam3 = lam4 ^ ((lane >> 3) & 1u);
    const unsigned lam2 = lam3 ^ ((lane >> 2) & 1u);
    const unsigned lam1 = lam2 ^ ((lane >> 1) & 1u);
    const unsigned lam0 = lam1 ^ (lane & 1u);

    // (4,5): ctrl = logical lane bit0 (lam0), tgt = reg bit2
    {
        const bool cs = lam0;
#pragma unroll
        for (int r = 0; r < 4; r++) {
            u64 t0 = a[r], t1 = a[r | 4];
            a[r]     = cs ? t1 : t0;
            a[r | 4] = cs ? t0 : t1;
        }
    }
    // (5,6): reg bit2 ctrl -> flip reg bit1:  a[4]<->a[6], a[5]<->a[7]
    { u64 t = a[4]; a[4] = a[6]; a[6] = t; t = a[5]; a[5] = a[7]; a[7] = t; }
    // (6,7): reg bit1 ctrl -> flip reg bit0:  a[2]<->a[3], a[6]<->a[7]
    { u64 t = a[2]; a[2] = a[3]; a[3] = t; t = a[6]; a[6] = a[7]; a[7] = t; }
    // (7,0): reg bit0 ctrl -> flip logical lane bit4 (mask 24)
#pragma unroll
    for (int r = 1; r < 8; r += 2) a[r] = shflx2(a[r], 24);

    // ===== re-encode RY(theta/2) under relabeling =====
    ry_lane_m(a, cq[0], sq[0], 24, lam4);
    ry_lane_m(a, cq[1], sq[1], 12, lam3);
    ry_lane_m(a, cq[2], sq[2],  6, lam2);
    ry_lane_m(a, cq[3], sq[3],  3, lam1);
    ry_lane_m(a, cq[4], sq[4],  1, lam0);
    ry_reg_m(a, cq[5], sq[5], 4);
    ry_reg_m(a, cq[6], sq[6], 2);
    ry_reg_m(a, cq[7], sq[7], 1);

    // DIAG3: re-encode RZ(phi/2) + layer1 Rot-RZ(phi_w), relabeled lane signs
    {
        float hc[8];
#pragma unroll
        for (int k = 0; k < NQ; k++) hc[k] = fmaf(0.25f, ph[k], g_hw[2][k]);
        float base = (lam4 ? hc[0] : -hc[0]) + (lam3 ? hc[1] : -hc[1])
                   + (lam2 ? hc[2] : -hc[2]) + (lam1 ? hc[3] : -hc[3])
                   + (lam0 ? hc[4] : -hc[4]);
        diag_gate_base(a, base, hc[5], hc[6], hc[7]);
    }

    // ===== layer 1 Rot-RY under relabeling =====
    {
        float c[8], s[8];
#pragma unroll
        for (int k = 0; k < NQ; k++) { float2 cs = g_vqc_cs[NQ + k]; c[k] = cs.x; s[k] = cs.y; }
        ry_lane_m(a, c[0], s[0], 24, lam4);
        ry_lane_m(a, c[1], s[1], 12, lam3);
        ry_lane_m(a, c[2], s[2],  6, lam2);
        ry_lane_m(a, c[3], s[3],  3, lam1);
        ry_lane_m(a, c[4], s[4],  1, lam0);
        ry_reg_m(a, c[5], s[5], 4);
        ry_reg_m(a, c[6], s[6], 2);
        ry_reg_m(a, c[7], s[7], 1);
    }

    // DIAG4 (layer1 Rot-RZ omega): diagonal before permutation+measurement -> no-op. Deleted.
    // CNOT ring 2: folded into measurement characters below.

    // ===== expectations: <Z_k>_final = <chi_{M_k}>_pre-ring2 =====
    // Reg-WHT gives channels mu; lane-WHT over each channel gives lane masks.
    // (lane mask, reg mask) per output (after relabel transform):
    //  Z0:(3,2) Z1:(30,5) Z2:(12,0) Z3:(6,0) Z4:(19,0) Z5:(6,4) Z6:(19,2) Z7:(6,5)
    float pw[8];
#pragma unroll
    for (int r = 0; r < 8; r++) {
        float x, y; upk(a[r], x, y);
        pw[r] = fmaf(x, x, y * y);
    }
#pragma unroll
    for (int st = 1; st < 8; st <<= 1) {
#pragma unroll
        for (int i = 0; i < 8; i++) {
            if (!(i & st)) {
                float u = pw[i], v = pw[i | st];
                pw[i] = u + v; pw[i | st] = u - v;
            }
        }
    }
    float v0 = lane_wht(pw[0], lane);
    float v2 = lane_wht(pw[2], lane);
    float v4 = lane_wht(pw[4], lane);
    float v5 = lane_wht(pw[5], lane);

    float* ob = out + (size_t)b * NQ;
    if (lane == 3)  ob[0] = v2;
    if (lane == 30) ob[1] = v5;
    if (lane == 12) ob[2] = v0;
    if (lane == 6)  { ob[3] = v0; ob[5] = v4; ob[7] = v5; }
    if (lane == 19) { ob[4] = v0; ob[6] = v2; }
}

extern "C" void kernel_launch(void* const* d_in, const int* in_sizes, int n_in,
                              void* d_out, int out_size) {
    const float* theta = (const float*)d_in[0];
    const float* phi   = (const float*)d_in[1];
    const float* jup   = (const float*)d_in[2];
    const float* w     = (const float*)d_in[3];
    float* out = (float*)d_out;

    precompute_vqc<<<1, 32>>>(w);
    const int grid = (NB * 32) / THREADS;
    vqc_kernel<<<grid, THREADS>>>(theta, phi, jup, w, out);
}

// round 5
// speedup vs baseline: 1.0306x; 1.0306x over previous
#include <cuda_runtime.h>
#include <stdint.h>

#define NQ      8
#define NPAIRS  28
#define NB      16384
#define THREADS 128

typedef unsigned long long u64;

// batch-shared precomputed constants
__device__ float2 g_vqc_cs[2 * NQ];          // cos/sin(theta_w/2) per (layer,qubit)
__device__ float  g_hw0[NQ];                 // 0.5*phi_w(l0)
__device__ float  g_hw2p[NQ];                // 0.5*phi_w(l1) - 0.25*phi_w(l0)
__device__ __align__(16) u64 g_d2[32][8];    // DIAG2 complex factors per (lane, r)

__global__ void precompute_vqc(const float* __restrict__ w) {
    int i = threadIdx.x;
    if (i < 2 * NQ) {
        float th = w[i * 3 + 1];
        float c, s;
        __sincosf(0.5f * th, &s, &c);
        g_vqc_cs[i] = make_float2(c, s);
    }
    if (i < NQ) {
        g_hw0[i]  = 0.5f * w[i * 3 + 0];
        g_hw2p[i] = 0.5f * w[(NQ + i) * 3 + 0] - 0.25f * w[i * 3 + 0];
    }
    // DIAG2 table: phase(lane,r) = sum_k (bit_k ? +h : -h), h_k = 0.5*omega_w(l0,k)
    // accurate host-grade sincos (runs once)
    {
        int lane = i;   // 32 threads
        float h[8];
        for (int k = 0; k < NQ; k++) h[k] = 0.5f * w[k * 3 + 2];
        float base = 0.f;
        for (int k = 0; k < 5; k++)
            base += ((lane >> (4 - k)) & 1) ? h[k] : -h[k];
        for (int r = 0; r < 8; r++) {
            float phr = base;
            phr += ((r >> 2) & 1) ? h[5] : -h[5];
            phr += ((r >> 1) & 1) ? h[6] : -h[6];
            phr += (r & 1) ? h[7] : -h[7];
            float ss, cc;
            sincosf(phr, &ss, &cc);
            u64 v; asm("mov.b64 %0, {%1, %2};" : "=l"(v) : "f"(cc), "f"(ss));
            g_d2[lane][r] = v;
        }
    }
}

// ---------------- f32x2 packed helpers ----------------
__device__ __forceinline__ u64 pk(float lo, float hi) {
    u64 v; asm("mov.b64 %0, {%1, %2};" : "=l"(v) : "f"(lo), "f"(hi)); return v;
}
__device__ __forceinline__ void upk(u64 v, float& lo, float& hi) {
    asm("mov.b64 {%0, %1}, %2;" : "=f"(lo), "=f"(hi) : "l"(v));
}
__device__ __forceinline__ u64 bc2(float x) { return pk(x, x); }
__device__ __forceinline__ u64 fma2(u64 a, u64 b, u64 c) {
    u64 d; asm("fma.rn.f32x2 %0, %1, %2, %3;" : "=l"(d) : "l"(a), "l"(b), "l"(c)); return d;
}
__device__ __forceinline__ u64 mul2(u64 a, u64 b) {
    u64 d; asm("mul.rn.f32x2 %0, %1, %2;" : "=l"(d) : "l"(a), "l"(b)); return d;
}
__device__ __forceinline__ u64 shflx2(u64 v, int m) {
    float lo, hi; upk(v, lo, hi);
    lo = __shfl_xor_sync(0xffffffffu, lo, m);
    hi = __shfl_xor_sync(0xffffffffu, hi, m);
    return pk(lo, hi);
}

// ---------------- gate primitives ----------------
// State: s = lane*8 + r. Qubit k -> state bit 7-k.

__device__ __forceinline__ void ry_lane_m(u64 (&a)[8], float c, float s,
                                          int mask, unsigned lam) {
    const u64 c2 = bc2(c);
    const u64 sg2 = bc2(lam ? s : -s);
#pragma unroll
    for (int r = 0; r < 8; r++) {
        u64 p = shflx2(a[r], mask);
        a[r] = fma2(sg2, p, mul2(c2, a[r]));
    }
}

__device__ __forceinline__ void ry_reg_m(u64 (&a)[8], float c, float s, int m) {
    const u64 c2 = bc2(c), s2 = bc2(s), ns2 = bc2(-s);
#pragma unroll
    for (int r = 0; r < 8; r++) {
        if (!(r & m)) {
            u64 x = a[r], y = a[r | m];
            a[r]     = fma2(ns2, y, mul2(c2, x));
            a[r | m] = fma2(s2,  x, mul2(c2, y));
        }
    }
}

// Diagonal phase gate (no range reduction — |phase| < ~12 here).
__device__ __forceinline__ void diag_gate_base(u64 (&a)[8], float base,
                                               float h5, float h6, float h7) {
    float w0[8] = { base, -h7, -h6, 0.f, -h5, 0.f, 0.f, 0.f };
#pragma unroll
    for (int st = 1; st < 8; st <<= 1) {
#pragma unroll
        for (int i = 0; i < 8; i++) {
            if (!(i & st)) {
                float u = w0[i], v = w0[i | st];
                w0[i] = u + v; w0[i | st] = u - v;
            }
        }
    }
#pragma unroll
    for (int r = 0; r < 8; r++) {
        float cc, ss;
        __sincosf(w0[r], &ss, &cc);
        float x, y; upk(a[r], x, y);
        a[r] = pk(fmaf(cc, x, -ss * y), fmaf(cc, y, ss * x));
    }
}

__device__ __forceinline__ float lane_wht(float v, unsigned lane) {
#pragma unroll
    for (int m = 1; m < 32; m <<= 1) {
        float t = __shfl_xor_sync(0xffffffffu, v, m);
        v = (lane & m) ? (t - v) : (v + t);
    }
    return v;
}

// ---------------- main kernel ----------------

__global__ void __launch_bounds__(THREADS, 9)
vqc_kernel(const float* __restrict__ theta, const float* __restrict__ phi,
           const float* __restrict__ jup, const float* __restrict__ w,
           float* __restrict__ out) {
    const unsigned tid  = blockIdx.x * THREADS + threadIdx.x;
    const unsigned b    = tid >> 5;
    const unsigned lane = tid & 31;

    float hc1[NQ];          // 0.5*phi + 0.5*phi_w(l0)   (DIAG1 coeffs; DIAG3 derives from these)
    float cq[NQ], sq[NQ];   // cos/sin(theta/4)
    float ch[NQ], sh[NQ];   // cos/sin(theta/2) via double-angle
#pragma unroll
    for (int k = 0; k < NQ; k++) {
        float th = theta[b * NQ + k];
        hc1[k] = fmaf(0.5f, phi[b * NQ + k], g_hw0[k]);
        __sincosf(0.25f * th, &sq[k], &cq[k]);
        sh[k] = 2.f * sq[k] * cq[k];
        ch[k] = fmaf(-2.f * sq[k], sq[k], 1.f);
    }

    // ===== Ising Walsh table over reg bits (lane part in index 0) =====
    float exr[8];
    {
        const float HP = 1.5707963267948966f;
        float il = 0.f, U0 = 0.f, U1 = 0.f, U2 = 0.f;
        float J56 = 0.f, J57 = 0.f, J67 = 0.f;
        int p = 0;
#pragma unroll
        for (int i = 0; i < 8; i++) {
#pragma unroll
            for (int j = i + 1; j < 8; j++) {
                float J = jup[(size_t)b * NPAIRS + p];
                if (j < 5) {
                    int d = ((lane >> (4 - i)) ^ (lane >> (4 - j))) & 1;
                    il += d ? J : -J;
                } else if (i < 5) {
                    int bi = (lane >> (4 - i)) & 1;
                    float v = bi ? J : -J;
                    if (j == 5) U0 += v; else if (j == 6) U1 += v; else U2 += v;
                } else {
                    if (i == 5 && j == 6) J56 = J;
                    else if (i == 5 && j == 7) J57 = J;
                    else J67 = J;
                }
                p++;
            }
        }
        exr[0] = il * HP;  exr[1] = U2 * HP;   exr[2] = U1 * HP;  exr[3] = -J67 * HP;
        exr[4] = U0 * HP;  exr[5] = -J57 * HP; exr[6] = -J56 * HP; exr[7] = 0.f;
    }

    // ===== Fused: product state after encoding RY + DIAG1 phase =====
    u64 a[8];
    {
        float base = 0.f;
#pragma unroll
        for (int k = 0; k < 5; k++)
            base += ((lane >> (4 - k)) & 1) ? hc1[k] : -hc1[k];
        float w0[8];
        w0[0] = base + exr[0];   w0[1] = exr[1] - hc1[7];
        w0[2] = exr[2] - hc1[6]; w0[3] = exr[3];
        w0[4] = exr[4] - hc1[5]; w0[5] = exr[5];
        w0[6] = exr[6];          w0[7] = exr[7];
#pragma unroll
        for (int st = 1; st < 8; st <<= 1) {
#pragma unroll
            for (int i = 0; i < 8; i++) {
                if (!(i & st)) {
                    float u = w0[i], v = w0[i | st];
                    w0[i] = u + v; w0[i | st] = u - v;
                }
            }
        }
        float lf = 1.f;
#pragma unroll
        for (int k = 0; k < 5; k++)
            lf *= ((lane >> (4 - k)) & 1) ? sh[k] : ch[k];
        float f56[4];
        f56[0] = ch[5] * ch[6]; f56[1] = ch[5] * sh[6];
        f56[2] = sh[5] * ch[6]; f56[3] = sh[5] * sh[6];
#pragma unroll
        for (int r = 0; r < 8; r++) {
            float v = lf * f56[r >> 1] * ((r & 1) ? sh[7] : ch[7]);
            float phr = w0[r];
            float q = rintf(phr * 0.15915494309189535f);
            phr = fmaf(q, -6.2831855f, phr);
            float cc, ss;
            __sincosf(phr, &ss, &cc);
            a[r] = pk(v * cc, v * ss);
        }
    }

    // ===== layer 0 Rot-RY (identity mapping: masks 16,8,4,2,1) =====
    {
        float c[8], s[8];
#pragma unroll
        for (int k = 0; k < NQ; k++) { float2 cs = g_vqc_cs[k]; c[k] = cs.x; s[k] = cs.y; }
        ry_lane_m(a, c[0], s[0], 16, (lane >> 4) & 1u);
        ry_lane_m(a, c[1], s[1],  8, (lane >> 3) & 1u);
        ry_lane_m(a, c[2], s[2],  4, (lane >> 2) & 1u);
        ry_lane_m(a, c[3], s[3],  2, (lane >> 1) & 1u);
        ry_lane_m(a, c[4], s[4],  1,  lane       & 1u);
        ry_reg_m(a, c[5], s[5], 4);
        ry_reg_m(a, c[6], s[6], 2);
        ry_reg_m(a, c[7], s[7], 1);
    }

    // ===== DIAG2 via precomputed complex table =====
    {
        const ulonglong2* d2 = reinterpret_cast<const ulonglong2*>(&g_d2[lane][0]);
#pragma unroll
        for (int i = 0; i < 4; i++) {
            ulonglong2 v = d2[i];
            float cc, ss, x, y;
            upk(v.x, cc, ss); upk(a[2 * i], x, y);
            a[2 * i] = pk(fmaf(cc, x, -ss * y), fmaf(cc, y, ss * x));
            upk(v.y, cc, ss); upk(a[2 * i + 1], x, y);
            a[2 * i + 1] = pk(fmaf(cc, x, -ss * y), fmaf(cc, y, ss * x));
        }
    }

    // ===== CNOT ring 1: lane part folded into relabeling =====
    const unsigned lam4 = (lane >> 4) & 1u;
    const unsigned lam3 = lam4 ^ ((lane >> 3) & 1u);
    const unsigned lam2 = lam3 ^ ((lane >> 2) & 1u);
    const unsigned lam1 = lam2 ^ ((lane >> 1) & 1u);
    const unsigned lam0 = lam1 ^ (lane & 1u);

    // (4,5): ctrl = logical lane bit0 (lam0), tgt = reg bit2
    {
        const bool cs = lam0;
#pragma unroll
        for (int r = 0; r < 4; r++) {
            u64 t0 = a[r], t1 = a[r | 4];
            a[r]     = cs ? t1 : t0;
            a[r | 4] = cs ? t0 : t1;
        }
    }
    // (5,6): reg bit2 ctrl -> flip reg bit1
    { u64 t = a[4]; a[4] = a[6]; a[6] = t; t = a[5]; a[5] = a[7]; a[7] = t; }
    // (6,7): reg bit1 ctrl -> flip reg bit0
    { u64 t = a[2]; a[2] = a[3]; a[3] = t; t = a[6]; a[6] = a[7]; a[7] = t; }
    // (7,0): reg bit0 ctrl -> flip logical lane bit4 (mask 24)
#pragma unroll
    for (int r = 1; r < 8; r += 2) a[r] = shflx2(a[r], 24);

    // ===== re-encode RY(theta/2) under relabeling =====
    ry_lane_m(a, cq[0], sq[0], 24, lam4);
    ry_lane_m(a, cq[1], sq[1], 12, lam3);
    ry_lane_m(a, cq[2], sq[2],  6, lam2);
    ry_lane_m(a, cq[3], sq[3],  3, lam1);
    ry_lane_m(a, cq[4], sq[4],  1, lam0);
    ry_reg_m(a, cq[5], sq[5], 4);
    ry_reg_m(a, cq[6], sq[6], 2);
    ry_reg_m(a, cq[7], sq[7], 1);

    // ===== DIAG3: 0.25*phi + 0.5*phi_w(l1) == 0.5*hc1 + g_hw2p =====
    {
        float hc[8];
#pragma unroll
        for (int k = 0; k < NQ; k++) hc[k] = fmaf(0.5f, hc1[k], g_hw2p[k]);
        float base = (lam4 ? hc[0] : -hc[0]) + (lam3 ? hc[1] : -hc[1])
                   + (lam2 ? hc[2] : -hc[2]) + (lam1 ? hc[3] : -hc[3])
                   + (lam0 ? hc[4] : -hc[4]);
        diag_gate_base(a, base, hc[5], hc[6], hc[7]);
    }

    // ===== layer 1 Rot-RY under relabeling =====
    {
        float c[8], s[8];
#pragma unroll
        for (int k = 0; k < NQ; k++) { float2 cs = g_vqc_cs[NQ + k]; c[k] = cs.x; s[k] = cs.y; }
        ry_lane_m(a, c[0], s[0], 24, lam4);
        ry_lane_m(a, c[1], s[1], 12, lam3);
        ry_lane_m(a, c[2], s[2],  6, lam2);
        ry_lane_m(a, c[3], s[3],  3, lam1);
        ry_lane_m(a, c[4], s[4],  1, lam0);
        ry_reg_m(a, c[5], s[5], 4);
        ry_reg_m(a, c[6], s[6], 2);
        ry_reg_m(a, c[7], s[7], 1);
    }

    // DIAG4 deleted (diagonal before permutation+measurement = no-op).
    // CNOT ring 2 folded into measurement characters.

    // ===== expectations: <Z_k>_final = <chi_{M_k}>_pre-ring2 =====
    float pw[8];
#pragma unroll
    for (int r = 0; r < 8; r++) {
        float x, y; upk(a[r], x, y);
        pw[r] = fmaf(x, x, y * y);
    }
#pragma unroll
    for (int st = 1; st < 8; st <<= 1) {
#pragma unroll
        for (int i = 0; i < 8; i++) {
            if (!(i & st)) {
                float u = pw[i], v = pw[i | st];
                pw[i] = u + v; pw[i | st] = u - v;
            }
        }
    }
    float v0 = lane_wht(pw[0], lane);
    float v2 = lane_wht(pw[2], lane);
    float v4 = lane_wht(pw[4], lane);
    float v5 = lane_wht(pw[5], lane);

    float* ob = out + (size_t)b * NQ;
    if (lane == 3)  ob[0] = v2;
    if (lane == 30) ob[1] = v5;
    if (lane == 12) ob[2] = v0;
    if (lane == 6)  { ob[3] = v0; ob[5] = v4; ob[7] = v5; }
    if (lane == 19) { ob[4] = v0; ob[6] = v2; }
}

extern "C" void kernel_launch(void* const* d_in, const int* in_sizes, int n_in,
                              void* d_out, int out_size) {
    const float* theta = (const float*)d_in[0];
    const float* phi   = (const float*)d_in[1];
    const float* jup   = (const float*)d_in[2];
    const float* w     = (const float*)d_in[3];
    float* out = (float*)d_out;

    precompute_vqc<<<1, 32>>>(w);
    const int grid = (NB * 32) / THREADS;
    vqc_kernel<<<grid, THREADS>>>(theta, phi, jup, w, out);
}

// round 6
// speedup vs baseline: 1.0750x; 1.0432x over previous
#include <cuda_runtime.h>
#include <stdint.h>

#define NQ      8
#define NPAIRS  28
#define NB      16384
#define THREADS 128

typedef unsigned long long u64;

// batch-shared precomputed constants
__device__ float2 g_vqc_cs[2 * NQ];          // cos/sin(theta_w/2) per (layer,qubit)
__device__ float  g_hw0[NQ];                 // 0.5*phi_w(l0)
__device__ float  g_hw2p[NQ];                // 0.5*phi_w(l1) - 0.25*phi_w(l0)
__device__ __align__(16) u64 g_d2[32][8];    // DIAG2 complex factors per (lane, r)

__global__ void precompute_vqc(const float* __restrict__ w) {
    int i = threadIdx.x;
    if (i < 2 * NQ) {
        float th = w[i * 3 + 1];
        float c, s;
        __sincosf(0.5f * th, &s, &c);
        g_vqc_cs[i] = make_float2(c, s);
    }
    if (i < NQ) {
        g_hw0[i]  = 0.5f * w[i * 3 + 0];
        g_hw2p[i] = 0.5f * w[(NQ + i) * 3 + 0] - 0.25f * w[i * 3 + 0];
    }
    // DIAG2 table: phase(lane,r) = sum_k (bit_k ? +h : -h), h_k = 0.5*omega_w(l0,k)
    {
        int lane = i;   // 32 threads
        float h[8];
        for (int k = 0; k < NQ; k++) h[k] = 0.5f * w[k * 3 + 2];
        float base = 0.f;
        for (int k = 0; k < 5; k++)
            base += ((lane >> (4 - k)) & 1) ? h[k] : -h[k];
        for (int r = 0; r < 8; r++) {
            float phr = base;
            phr += ((r >> 2) & 1) ? h[5] : -h[5];
            phr += ((r >> 1) & 1) ? h[6] : -h[6];
            phr += (r & 1) ? h[7] : -h[7];
            float ss, cc;
            sincosf(phr, &ss, &cc);
            u64 v; asm("mov.b64 %0, {%1, %2};" : "=l"(v) : "f"(cc), "f"(ss));
            g_d2[lane][r] = v;
        }
    }
}

// ---------------- f32x2 packed helpers ----------------
__device__ __forceinline__ u64 pk(float lo, float hi) {
    u64 v; asm("mov.b64 %0, {%1, %2};" : "=l"(v) : "f"(lo), "f"(hi)); return v;
}
__device__ __forceinline__ void upk(u64 v, float& lo, float& hi) {
    asm("mov.b64 {%0, %1}, %2;" : "=f"(lo), "=f"(hi) : "l"(v));
}
__device__ __forceinline__ u64 bc2(float x) { return pk(x, x); }
__device__ __forceinline__ u64 sw2(u64 v) {   // (x,y) -> (y,x)
    float lo, hi; upk(v, lo, hi); return pk(hi, lo);
}
__device__ __forceinline__ u64 fma2(u64 a, u64 b, u64 c) {
    u64 d; asm("fma.rn.f32x2 %0, %1, %2, %3;" : "=l"(d) : "l"(a), "l"(b), "l"(c)); return d;
}
__device__ __forceinline__ u64 mul2(u64 a, u64 b) {
    u64 d; asm("mul.rn.f32x2 %0, %1, %2;" : "=l"(d) : "l"(a), "l"(b)); return d;
}
__device__ __forceinline__ u64 shflx2(u64 v, int m) {
    float lo, hi; upk(v, lo, hi);
    lo = __shfl_xor_sync(0xffffffffu, lo, m);
    hi = __shfl_xor_sync(0xffffffffu, hi, m);
    return pk(lo, hi);
}

// ---------------- gate primitives ----------------
// State: s = lane*8 + r. Qubit k -> state bit 7-k.

__device__ __forceinline__ void ry_lane_m(u64 (&a)[8], float c, float s,
                                          int mask, unsigned lam) {
    const u64 c2 = bc2(c);
    const u64 sg2 = bc2(lam ? s : -s);
#pragma unroll
    for (int r = 0; r < 8; r++) {
        u64 p = shflx2(a[r], mask);
        a[r] = fma2(sg2, p, mul2(c2, a[r]));
    }
}

__device__ __forceinline__ void ry_reg_m(u64 (&a)[8], float c, float s, int m) {
    const u64 c2 = bc2(c), s2 = bc2(s), ns2 = bc2(-s);
#pragma unroll
    for (int r = 0; r < 8; r++) {
        if (!(r & m)) {
            u64 x = a[r], y = a[r | m];
            a[r]     = fma2(ns2, y, mul2(c2, x));
            a[r | m] = fma2(s2,  x, mul2(c2, y));
        }
    }
}

__device__ __forceinline__ float lane_wht(float v, unsigned lane) {
#pragma unroll
    for (int m = 1; m < 32; m <<= 1) {
        float t = __shfl_xor_sync(0xffffffffu, v, m);
        v = (lane & m) ? (t - v) : (v + t);
    }
    return v;
}

// ---------------- main kernel ----------------

__global__ void __launch_bounds__(THREADS)
vqc_kernel(const float* __restrict__ theta, const float* __restrict__ phi,
           const float* __restrict__ jup, const float* __restrict__ w,
           float* __restrict__ out) {
    const unsigned tid  = blockIdx.x * THREADS + threadIdx.x;
    const unsigned b    = tid >> 5;
    const unsigned lane = tid & 31;

    float hc1[NQ];          // 0.5*phi + 0.5*phi_w(l0)
    float cq[NQ], sq[NQ];   // cos/sin(theta/4)
    float ch[NQ], sh[NQ];   // cos/sin(theta/2) via double-angle
#pragma unroll
    for (int k = 0; k < NQ; k++) {
        float th = theta[b * NQ + k];
        hc1[k] = fmaf(0.5f, phi[b * NQ + k], g_hw0[k]);
        __sincosf(0.25f * th, &sq[k], &cq[k]);
        sh[k] = 2.f * sq[k] * cq[k];
        ch[k] = fmaf(-2.f * sq[k], sq[k], 1.f);
    }

    // ===== Ising Walsh table over reg bits (lane part in index 0) =====
    float exr[8];
    {
        const float HP = 1.5707963267948966f;
        float il = 0.f, U0 = 0.f, U1 = 0.f, U2 = 0.f;
        float J56 = 0.f, J57 = 0.f, J67 = 0.f;
        int p = 0;
#pragma unroll
        for (int i = 0; i < 8; i++) {
#pragma unroll
            for (int j = i + 1; j < 8; j++) {
                float J = jup[(size_t)b * NPAIRS + p];
                if (j < 5) {
                    int d = ((lane >> (4 - i)) ^ (lane >> (4 - j))) & 1;
                    il += d ? J : -J;
                } else if (i < 5) {
                    int bi = (lane >> (4 - i)) & 1;
                    float v = bi ? J : -J;
                    if (j == 5) U0 += v; else if (j == 6) U1 += v; else U2 += v;
                } else {
                    if (i == 5 && j == 6) J56 = J;
                    else if (i == 5 && j == 7) J57 = J;
                    else J67 = J;
                }
                p++;
            }
        }
        exr[0] = il * HP;  exr[1] = U2 * HP;   exr[2] = U1 * HP;  exr[3] = -J67 * HP;
        exr[4] = U0 * HP;  exr[5] = -J57 * HP; exr[6] = -J56 * HP; exr[7] = 0.f;
    }

    // ===== Fused: product state after encoding RY + DIAG1 phase =====
    u64 a[8];
    {
        float base = 0.f;
#pragma unroll
        for (int k = 0; k < 5; k++)
            base += ((lane >> (4 - k)) & 1) ? hc1[k] : -hc1[k];
        float w0[8];
        w0[0] = base + exr[0];   w0[1] = exr[1] - hc1[7];
        w0[2] = exr[2] - hc1[6]; w0[3] = exr[3];
        w0[4] = exr[4] - hc1[5]; w0[5] = exr[5];
        w0[6] = exr[6];          w0[7] = exr[7];
#pragma unroll
        for (int st = 1; st < 8; st <<= 1) {
#pragma unroll
            for (int i = 0; i < 8; i++) {
                if (!(i & st)) {
                    float u = w0[i], v = w0[i | st];
                    w0[i] = u + v; w0[i | st] = u - v;
                }
            }
        }
        float lf = 1.f;
#pragma unroll
        for (int k = 0; k < 5; k++)
            lf *= ((lane >> (4 - k)) & 1) ? sh[k] : ch[k];
        float f56[4];
        f56[0] = ch[5] * ch[6]; f56[1] = ch[5] * sh[6];
        f56[2] = sh[5] * ch[6]; f56[3] = sh[5] * sh[6];
#pragma unroll
        for (int r = 0; r < 8; r++) {
            float v = lf * f56[r >> 1] * ((r & 1) ? sh[7] : ch[7]);
            float phr = w0[r];
            float q = rintf(phr * 0.15915494309189535f);
            phr = fmaf(q, -6.2831855f, phr);
            float cc, ss;
            __sincosf(phr, &ss, &cc);
            a[r] = pk(v * cc, v * ss);
        }
    }

    // ===== Round A: layer 0 Rot-RY (identity mapping: masks 16,8,4,2,1) =====
    {
        float c[8], s[8];
#pragma unroll
        for (int k = 0; k < NQ; k++) { float2 cs = g_vqc_cs[k]; c[k] = cs.x; s[k] = cs.y; }
        ry_lane_m(a, c[0], s[0], 16, (lane >> 4) & 1u);
        ry_lane_m(a, c[1], s[1],  8, (lane >> 3) & 1u);
        ry_lane_m(a, c[2], s[2],  4, (lane >> 2) & 1u);
        ry_lane_m(a, c[3], s[3],  2, (lane >> 1) & 1u);
        ry_lane_m(a, c[4], s[4],  1,  lane       & 1u);
        ry_reg_m(a, c[5], s[5], 4);
        ry_reg_m(a, c[6], s[6], 2);
        ry_reg_m(a, c[7], s[7], 1);
    }

    // ===== DIAG2 via precomputed complex table =====
    {
        const ulonglong2* d2 = reinterpret_cast<const ulonglong2*>(&g_d2[lane][0]);
#pragma unroll
        for (int i = 0; i < 4; i++) {
            ulonglong2 v = d2[i];
            float cc, ss, x, y;
            upk(v.x, cc, ss); upk(a[2 * i], x, y);
            a[2 * i] = pk(fmaf(cc, x, -ss * y), fmaf(cc, y, ss * x));
            upk(v.y, cc, ss); upk(a[2 * i + 1], x, y);
            a[2 * i + 1] = pk(fmaf(cc, x, -ss * y), fmaf(cc, y, ss * x));
        }
    }

    // ===== CNOT ring 1: lane part folded into relabeling =====
    const unsigned lam4 = (lane >> 4) & 1u;
    const unsigned lam3 = lam4 ^ ((lane >> 3) & 1u);
    const unsigned lam2 = lam3 ^ ((lane >> 2) & 1u);
    const unsigned lam1 = lam2 ^ ((lane >> 1) & 1u);
    const unsigned lam0 = lam1 ^ (lane & 1u);

    // (4,5): ctrl = logical lane bit0 (lam0), tgt = reg bit2
    {
        const bool cs = lam0;
#pragma unroll
        for (int r = 0; r < 4; r++) {
            u64 t0 = a[r], t1 = a[r | 4];
            a[r]     = cs ? t1 : t0;
            a[r | 4] = cs ? t0 : t1;
        }
    }
    // (5,6): reg bit2 ctrl -> flip reg bit1
    { u64 t = a[4]; a[4] = a[6]; a[6] = t; t = a[5]; a[5] = a[7]; a[7] = t; }
    // (6,7): reg bit1 ctrl -> flip reg bit0
    { u64 t = a[2]; a[2] = a[3]; a[3] = t; t = a[6]; a[6] = a[7]; a[7] = t; }
    // (7,0): reg bit0 ctrl -> flip logical lane bit4 (mask 24)
#pragma unroll
    for (int r = 1; r < 8; r += 2) a[r] = shflx2(a[r], 24);

    // ===== Round B: per-qubit general gate U = RY(psi1) * RZ(2*hc3) * RY(theta/2-enc) =====
    // One exchange per lane qubit (was two RY rounds + DIAG3).
    {
        const int  MSK[5]  = { 24, 12, 6, 3, 1 };
        const unsigned LAMV[5] = { lam4, lam3, lam2, lam1, lam0 };
#pragma unroll
        for (int k = 0; k < NQ; k++) {
            float hc3 = fmaf(0.5f, hc1[k], g_hw2p[k]);
            float cd, sd;
            __sincosf(hc3, &sd, &cd);
            float2 pw = g_vqc_cs[NQ + k];               // cos/sin(psi1/2)
            float t1 = pw.x * cq[k], t2 = pw.y * sq[k];
            float t3 = pw.x * sq[k], t4 = pw.y * cq[k];
            float P = t1 - t2, Q = t1 + t2, R = t3 + t4, S = t4 - t3;
            float cdP = cd * P, sdQ = sd * Q, cdR = cd * R, sdS = sd * S;
            // u00=(cdP,-sdQ) u01=(-cdR,-sdS) u10=(cdR,-sdS) u11=(cdP,sdQ)
            if (k < 5) {
                const unsigned bb = LAMV[k];
                const float csy = bb ? sdQ : -sdQ;
                const float cpx = bb ? cdR : -cdR;
                const u64 A0 = bc2(cdP), A1 = pk(-csy, csy);
                const u64 B0 = bc2(cpx), B1 = pk(sdS, -sdS);
#pragma unroll
                for (int r = 0; r < 8; r++) {
                    u64 p = shflx2(a[r], MSK[k]);
                    a[r] = fma2(B1, sw2(p),
                           fma2(B0, p,
                           fma2(A1, sw2(a[r]), mul2(A0, a[r]))));
                }
            } else {
                const int m = 1 << (7 - k);              // 4,2,1
                const u64 C0 = bc2(cdP);
                const u64 Cl = pk(sdQ, -sdQ), Ch = pk(-sdQ, sdQ);
                const u64 D0n = bc2(-cdR), D0p = bc2(cdR);
                const u64 D1 = pk(sdS, -sdS);
#pragma unroll
                for (int r = 0; r < 8; r++) {
                    if (!(r & m)) {
                        u64 lo = a[r], hi = a[r | m];
                        u64 swl = sw2(lo), swh = sw2(hi);
                        a[r]     = fma2(D1, swh, fma2(D0n, hi,
                                   fma2(Cl, swl, mul2(C0, lo))));
                        a[r | m] = fma2(Ch, swh, fma2(C0, hi,
                                   fma2(D1, swl, mul2(D0p, lo))));
                    }
                }
            }
        }
    }

    // DIAG4 deleted (diagonal before permutation+measurement = no-op).
    // CNOT ring 2 folded into measurement characters.

    // ===== expectations: <Z_k>_final = <chi_{M_k}>_pre-ring2 =====
    float pwv[8];
#pragma unroll
    for (int r = 0; r < 8; r++) {
        float x, y; upk(a[r], x, y);
        pwv[r] = fmaf(x, x, y * y);
    }
#pragma unroll
    for (int st = 1; st < 8; st <<= 1) {
#pragma unroll
        for (int i = 0; i < 8; i++) {
            if (!(i & st)) {
                float u = pwv[i], v = pwv[i | st];
                pwv[i] = u + v; pwv[i | st] = u - v;
            }
        }
    }
    float v0 = lane_wht(pwv[0], lane);
    float v2 = lane_wht(pwv[2], lane);
    float v4 = lane_wht(pwv[4], lane);
    float v5 = lane_wht(pwv[5], lane);

    float* ob = out + (size_t)b * NQ;
    if (lane == 3)  ob[0] = v2;
    if (lane == 30) ob[1] = v5;
    if (lane == 12) ob[2] = v0;
    if (lane == 6)  { ob[3] = v0; ob[5] = v4; ob[7] = v5; }
    if (lane == 19) { ob[4] = v0; ob[6] = v2; }
}

extern "C" void kernel_launch(void* const* d_in, const int* in_sizes, int n_in,
                              void* d_out, int out_size) {
    const float* theta = (const float*)d_in[0];
    const float* phi   = (const float*)d_in[1];
    const float* jup   = (const float*)d_in[2];
    const float* w     = (const float*)d_in[3];
    float* out = (float*)d_out;

    precompute_vqc<<<1, 32>>>(w);
    const int grid = (NB * 32) / THREADS;
    vqc_kernel<<<grid, THREADS>>>(theta, phi, jup, w, out);
}

// round 8
// speedup vs baseline: 1.0946x; 1.0181x over previous
#include <cuda_runtime.h>
#include <stdint.h>

#define NQ      8
#define NPAIRS  28
#define NB      16384
#define THREADS 128

typedef unsigned long long u64;

// batch-shared precomputed constants
__device__ float2 g_vqc_cs[2 * NQ];          // cos/sin(theta_w/2) per (layer,qubit)
__device__ float  g_hw0[NQ];                 // 0.5*phi_w(l0)
__device__ float  g_hw2p[NQ];                // 0.5*phi_w(l1) - 0.25*phi_w(l0)
__device__ __align__(16) u64 g_d2[32][8];    // DIAG2 complex factors per (lane, r)

// Fully parallel: 256 threads, one (lane,r) table entry each; first 16/8 also
// fill the small tables. __sincosf is fine here (|arg| small, budget 1e-3).
__global__ void precompute_vqc(const float* __restrict__ w) {
    int i = threadIdx.x;
    if (i < 2 * NQ) {
        float c, s;
        __sincosf(0.5f * w[i * 3 + 1], &s, &c);
        g_vqc_cs[i] = make_float2(c, s);
    }
    if (i < NQ) {
        g_hw0[i]  = 0.5f * w[i * 3 + 0];
        g_hw2p[i] = 0.5f * w[(NQ + i) * 3 + 0] - 0.25f * w[i * 3 + 0];
    }
    {
        int lane = i >> 3, r = i & 7;
        float phr = 0.f;
#pragma unroll
        for (int k = 0; k < 5; k++) {
            float h = 0.5f * w[k * 3 + 2];
            phr += ((lane >> (4 - k)) & 1) ? h : -h;
        }
        phr += ((r >> 2) & 1) ? 0.5f * w[5 * 3 + 2] : -0.5f * w[5 * 3 + 2];
        phr += ((r >> 1) & 1) ? 0.5f * w[6 * 3 + 2] : -0.5f * w[6 * 3 + 2];
        phr += (r & 1)        ? 0.5f * w[7 * 3 + 2] : -0.5f * w[7 * 3 + 2];
        float ss, cc;
        __sincosf(phr, &ss, &cc);
        u64 v; asm("mov.b64 %0, {%1, %2};" : "=l"(v) : "f"(cc), "f"(ss));
        g_d2[lane][r] = v;
    }
}

// ---------------- f32x2 packed helpers ----------------
__device__ __forceinline__ u64 pk(float lo, float hi) {
    u64 v; asm("mov.b64 %0, {%1, %2};" : "=l"(v) : "f"(lo), "f"(hi)); return v;
}
__device__ __forceinline__ void upk(u64 v, float& lo, float& hi) {
    asm("mov.b64 {%0, %1}, %2;" : "=f"(lo), "=f"(hi) : "l"(v));
}
__device__ __forceinline__ u64 bc2(float x) { return pk(x, x); }
__device__ __forceinline__ u64 sw2(u64 v) {
    float lo, hi; upk(v, lo, hi); return pk(hi, lo);
}
__device__ __forceinline__ u64 fma2(u64 a, u64 b, u64 c) {
    u64 d; asm("fma.rn.f32x2 %0, %1, %2, %3;" : "=l"(d) : "l"(a), "l"(b), "l"(c)); return d;
}
__device__ __forceinline__ u64 mul2(u64 a, u64 b) {
    u64 d; asm("mul.rn.f32x2 %0, %1, %2;" : "=l"(d) : "l"(a), "l"(b)); return d;
}
__device__ __forceinline__ u64 shflx2(u64 v, int m) {
    float lo, hi; upk(v, lo, hi);
    lo = __shfl_xor_sync(0xffffffffu, lo, m);
    hi = __shfl_xor_sync(0xffffffffu, hi, m);
    return pk(lo, hi);
}

// ---------------- gate primitives ----------------
__device__ __forceinline__ void ry_lane_m(u64 (&a)[8], float c, float s,
                                          int mask, unsigned lam) {
    const u64 c2 = bc2(c);
    const u64 sg2 = bc2(lam ? s : -s);
#pragma unroll
    for (int r = 0; r < 8; r++) {
        u64 p = shflx2(a[r], mask);
        a[r] = fma2(sg2, p, mul2(c2, a[r]));
    }
}

__device__ __forceinline__ void ry_reg_m(u64 (&a)[8], float c, float s, int m) {
    const u64 c2 = bc2(c), s2 = bc2(s), ns2 = bc2(-s);
#pragma unroll
    for (int r = 0; r < 8; r++) {
        if (!(r & m)) {
            u64 x = a[r], y = a[r | m];
            a[r]     = fma2(ns2, y, mul2(c2, x));
            a[r | m] = fma2(s2,  x, mul2(c2, y));
        }
    }
}

__device__ __forceinline__ float lane_wht(float v, unsigned lane) {
#pragma unroll
    for (int m = 1; m < 32; m <<= 1) {
        float t = __shfl_xor_sync(0xffffffffu, v, m);
        v = (lane & m) ? (t - v) : (v + t);
    }
    return v;
}

// ---------------- main kernel ----------------

__global__ void __launch_bounds__(THREADS, 8)
vqc_kernel(const float4* __restrict__ theta4, const float4* __restrict__ phi4,
           const float4* __restrict__ jup4, float* __restrict__ out) {
    const unsigned tid  = blockIdx.x * THREADS + threadIdx.x;
    const unsigned b    = tid >> 5;
    const unsigned lane = tid & 31;

    // vectorized warp-uniform loads
    float th[NQ], phv[NQ], J[NPAIRS];
    {
        float4 t0 = theta4[b * 2], t1 = theta4[b * 2 + 1];
        th[0]=t0.x; th[1]=t0.y; th[2]=t0.z; th[3]=t0.w;
        th[4]=t1.x; th[5]=t1.y; th[6]=t1.z; th[7]=t1.w;
        float4 p0 = phi4[b * 2], p1 = phi4[b * 2 + 1];
        phv[0]=p0.x; phv[1]=p0.y; phv[2]=p0.z; phv[3]=p0.w;
        phv[4]=p1.x; phv[5]=p1.y; phv[6]=p1.z; phv[7]=p1.w;
#pragma unroll
        for (int q = 0; q < 7; q++) {
            float4 jv = jup4[b * 7 + q];
            J[q*4+0]=jv.x; J[q*4+1]=jv.y; J[q*4+2]=jv.z; J[q*4+3]=jv.w;
        }
    }

    float hc1[NQ];          // 0.5*phi + 0.5*phi_w(l0)
    float cq[NQ], sq[NQ];   // cos/sin(theta/4)
    float ch[NQ], sh[NQ];   // cos/sin(theta/2) via double-angle
#pragma unroll
    for (int k = 0; k < NQ; k++) {
        hc1[k] = fmaf(0.5f, phv[k], g_hw0[k]);
        __sincosf(0.25f * th[k], &sq[k], &cq[k]);
        sh[k] = 2.f * sq[k] * cq[k];
        ch[k] = fmaf(-2.f * sq[k], sq[k], 1.f);
    }

    // ===== Ising Walsh table over reg bits (lane part in index 0) =====
    // Lexicographic pair index: row starts {0,7,13,18,22,25,27}
    float exr[8];
    {
        const float HP = 1.5707963267948966f;
        float sg[5];
#pragma unroll
        for (int k = 0; k < 5; k++)
            sg[k] = ((lane >> (4 - k)) & 1) ? 1.f : -1.f;
        // lane-lane pairs: mask = +1 if bits differ = -sg_i*sg_j
        float il = 0.f;
        {
            const int PI[10] = {0,0,0,0, 1,1,1, 2,2, 3};
            const int PJ[10] = {1,2,3,4, 2,3,4, 3,4, 4};
            const int PP[10] = {0,1,2,3, 7,8,9, 13,14, 18};
#pragma unroll
            for (int t = 0; t < 10; t++)
                il = fmaf(-sg[PI[t]] * sg[PJ[t]], J[PP[t]], il);
        }
        // lane-reg pairs: (i,5) at {4,10,15,19,22}; (i,6),(i,7) consecutive after
        float U0 = 0.f, U1 = 0.f, U2 = 0.f;
        {
            const int P5[5] = {4, 10, 15, 19, 22};
#pragma unroll
            for (int i = 0; i < 5; i++) {
                U0 = fmaf(sg[i], J[P5[i]],     U0);
                U1 = fmaf(sg[i], J[P5[i] + 1], U1);
                U2 = fmaf(sg[i], J[P5[i] + 2], U2);
            }
        }
        float J56 = J[25], J57 = J[26], J67 = J[27];
        exr[0] = il * HP;  exr[1] = U2 * HP;   exr[2] = U1 * HP;  exr[3] = -J67 * HP;
        exr[4] = U0 * HP;  exr[5] = -J57 * HP; exr[6] = -J56 * HP; exr[7] = 0.f;
    }

    // ===== Fused: product state after encoding RY + DIAG1 phase =====
    u64 a[8];
    {
        float base = 0.f;
#pragma unroll
        for (int k = 0; k < 5; k++)
            base += ((lane >> (4 - k)) & 1) ? hc1[k] : -hc1[k];
        float w0[8];
        w0[0] = base + exr[0];   w0[1] = exr[1] - hc1[7];
        w0[2] = exr[2] - hc1[6]; w0[3] = exr[3];
        w0[4] = exr[4] - hc1[5]; w0[5] = exr[5];
        w0[6] = exr[6];          w0[7] = exr[7];
#pragma unroll
        for (int st = 1; st < 8; st <<= 1) {
#pragma unroll
            for (int i = 0; i < 8; i++) {
                if (!(i & st)) {
                    float u = w0[i], v = w0[i | st];
                    w0[i] = u + v; w0[i | st] = u - v;
                }
            }
        }
        float lf = 1.f;
#pragma unroll
        for (int k = 0; k < 5; k++)
            lf *= ((lane >> (4 - k)) & 1) ? sh[k] : ch[k];
        float f56[4];
        f56[0] = ch[5] * ch[6]; f56[1] = ch[5] * sh[6];
        f56[2] = sh[5] * ch[6]; f56[3] = sh[5] * sh[6];
#pragma unroll
        for (int r = 0; r < 8; r++) {
            float v = lf * f56[r >> 1] * ((r & 1) ? sh[7] : ch[7]);
            float phr = w0[r];
            float q = rintf(phr * 0.15915494309189535f);
            phr = fmaf(q, -6.2831855f, phr);
            float cc, ss;
            __sincosf(phr, &ss, &cc);
            a[r] = pk(v * cc, v * ss);
        }
    }

    // ===== Round A: layer 0 Rot-RY =====
    {
        float c[8], s[8];
#pragma unroll
        for (int k = 0; k < NQ; k++) { float2 cs = g_vqc_cs[k]; c[k] = cs.x; s[k] = cs.y; }
        ry_lane_m(a, c[0], s[0], 16, (lane >> 4) & 1u);
        ry_lane_m(a, c[1], s[1],  8, (lane >> 3) & 1u);
        ry_lane_m(a, c[2], s[2],  4, (lane >> 2) & 1u);
        ry_lane_m(a, c[3], s[3],  2, (lane >> 1) & 1u);
        ry_lane_m(a, c[4], s[4],  1,  lane       & 1u);
        ry_reg_m(a, c[5], s[5], 4);
        ry_reg_m(a, c[6], s[6], 2);
        ry_reg_m(a, c[7], s[7], 1);
    }

    // ===== DIAG2 via precomputed complex table =====
    {
        const ulonglong2* d2 = reinterpret_cast<const ulonglong2*>(&g_d2[lane][0]);
#pragma unroll
        for (int i = 0; i < 4; i++) {
            ulonglong2 v = d2[i];
            float cc, ss, x, y;
            upk(v.x, cc, ss); upk(a[2 * i], x, y);
            a[2 * i] = pk(fmaf(cc, x, -ss * y), fmaf(cc, y, ss * x));
            upk(v.y, cc, ss); upk(a[2 * i + 1], x, y);
            a[2 * i + 1] = pk(fmaf(cc, x, -ss * y), fmaf(cc, y, ss * x));
        }
    }

    // ===== CNOT ring 1: lane part folded into relabeling =====
    const unsigned lam4 = (lane >> 4) & 1u;
    const unsigned lam3 = lam4 ^ ((lane >> 3) & 1u);
    const unsigned lam2 = lam3 ^ ((lane >> 2) & 1u);
    const unsigned lam1 = lam2 ^ ((lane >> 1) & 1u);
    const unsigned lam0 = lam1 ^ (lane & 1u);

    {
        const bool cs = lam0;
#pragma unroll
        for (int r = 0; r < 4; r++) {
            u64 t0 = a[r], t1 = a[r | 4];
            a[r]     = cs ? t1 : t0;
            a[r | 4] = cs ? t0 : t1;
        }
    }
    { u64 t = a[4]; a[4] = a[6]; a[6] = t; t = a[5]; a[5] = a[7]; a[7] = t; }
    { u64 t = a[2]; a[2] = a[3]; a[3] = t; t = a[6]; a[6] = a[7]; a[7] = t; }
#pragma unroll
    for (int r = 1; r < 8; r += 2) a[r] = shflx2(a[r], 24);

    // ===== Round B: per-qubit U = RY(psi1) * RZ(2*hc3) * RY(theta/2-enc) =====
    {
        const int  MSK[5]  = { 24, 12, 6, 3, 1 };
        const unsigned LAMV[5] = { lam4, lam3, lam2, lam1, lam0 };
#pragma unroll
        for (int k = 0; k < NQ; k++) {
            float hc3 = fmaf(0.5f, hc1[k], g_hw2p[k]);
            float cd, sd;
            __sincosf(hc3, &sd, &cd);
            float2 pw = g_vqc_cs[NQ + k];               // cos/sin(psi1/2)
            float t1 = pw.x * cq[k], t2 = pw.y * sq[k];
            float t3 = pw.x * sq[k], t4 = pw.y * cq[k];
            float P = t1 - t2, Q = t1 + t2, R = t3 + t4, S = t4 - t3;
            float cdP = cd * P, sdQ = sd * Q, cdR = cd * R, sdS = sd * S;
            if (k < 5) {
                const unsigned bb = LAMV[k];
                const float csy = bb ? sdQ : -sdQ;
                const float cpx = bb ? cdR : -cdR;
                const u64 A0 = bc2(cdP), A1 = pk(-csy, csy);
                const u64 B0 = bc2(cpx), B1 = pk(sdS, -sdS);
#pragma unroll
                for (int r = 0; r < 8; r++) {
                    u64 p = shflx2(a[r], MSK[k]);
                    a[r] = fma2(B1, sw2(p),
                           fma2(B0, p,
                           fma2(A1, sw2(a[r]), mul2(A0, a[r]))));
                }
            } else {
                const int m = 1 << (7 - k);
                const u64 C0 = bc2(cdP);
                const u64 Cl = pk(sdQ, -sdQ), Ch = pk(-sdQ, sdQ);
                const u64 D0n = bc2(-cdR), D0p = bc2(cdR);
                const u64 D1 = pk(sdS, -sdS);
#pragma unroll
                for (int r = 0; r < 8; r++) {
                    if (!(r & m)) {
                        u64 lo = a[r], hi = a[r | m];
                        u64 swl = sw2(lo), swh = sw2(hi);
                        a[r]     = fma2(D1, swh, fma2(D0n, hi,
                                   fma2(Cl, swl, mul2(C0, lo))));
                        a[r | m] = fma2(Ch, swh, fma2(C0, hi,
                                   fma2(D1, swl, mul2(D0p, lo))));
                    }
                }
            }
        }
    }

    // ===== expectations: <Z_k>_final = <chi_{M_k}>_pre-ring2 =====
    float pwv[8];
#pragma unroll
    for (int r = 0; r < 8; r++) {
        float x, y; upk(a[r], x, y);
        pwv[r] = fmaf(x, x, y * y);
    }
#pragma unroll
    for (int st = 1; st < 8; st <<= 1) {
#pragma unroll
        for (int i = 0; i < 8; i++) {
            if (!(i & st)) {
                float u = pwv[i], v = pwv[i | st];
                pwv[i] = u + v; pwv[i | st] = u - v;
            }
        }
    }
    float v0 = lane_wht(pwv[0], lane);
    float v2 = lane_wht(pwv[2], lane);
    float v4 = lane_wht(pwv[4], lane);
    float v5 = lane_wht(pwv[5], lane);

    float* ob = out + (size_t)b * NQ;
    if (lane == 3)  ob[0] = v2;
    if (lane == 30) ob[1] = v5;
    if (lane == 12) ob[2] = v0;
    if (lane == 6)  { ob[3] = v0; ob[5] = v4; ob[7] = v5; }
    if (lane == 19) { ob[4] = v0; ob[6] = v2; }
}

extern "C" void kernel_launch(void* const* d_in, const int* in_sizes, int n_in,
                              void* d_out, int out_size) {
    const float4* theta4 = (const float4*)d_in[0];
    const float4* phi4   = (const float4*)d_in[1];
    const float4* jup4   = (const float4*)d_in[2];
    const float*  w      = (const float*)d_in[3];
    float* out = (float*)d_out;

    precompute_vqc<<<1, 256>>>(w);
    const int grid = (NB * 32) / THREADS;
    vqc_kernel<<<grid, THREADS>>>(theta4, phi4, jup4, out);
}

// round 9
// speedup vs baseline: 1.1754x; 1.0738x over previous
#include <cuda_runtime.h>
#include <stdint.h>

#define NQ      8
#define NPAIRS  28
#define NB      16384
#define THREADS 128

typedef unsigned long long u64;

// ---------------- f32x2 packed helpers ----------------
__device__ __forceinline__ u64 pk(float lo, float hi) {
    u64 v; asm("mov.b64 %0, {%1, %2};" : "=l"(v) : "f"(lo), "f"(hi)); return v;
}
__device__ __forceinline__ void upk(u64 v, float& lo, float& hi) {
    asm("mov.b64 {%0, %1}, %2;" : "=f"(lo), "=f"(hi) : "l"(v));
}
__device__ __forceinline__ u64 bc2(float x) { return pk(x, x); }
__device__ __forceinline__ u64 sw2(u64 v) {
    float lo, hi; upk(v, lo, hi); return pk(hi, lo);
}
__device__ __forceinline__ u64 fma2(u64 a, u64 b, u64 c) {
    u64 d; asm("fma.rn.f32x2 %0, %1, %2, %3;" : "=l"(d) : "l"(a), "l"(b), "l"(c)); return d;
}
__device__ __forceinline__ u64 mul2(u64 a, u64 b) {
    u64 d; asm("mul.rn.f32x2 %0, %1, %2;" : "=l"(d) : "l"(a), "l"(b)); return d;
}
__device__ __forceinline__ u64 shflx2(u64 v, int m) {
    float lo, hi; upk(v, lo, hi);
    lo = __shfl_xor_sync(0xffffffffu, lo, m);
    hi = __shfl_xor_sync(0xffffffffu, hi, m);
    return pk(lo, hi);
}

// ---------------- gate primitives ----------------
__device__ __forceinline__ void ry_lane_m(u64 (&a)[8], float c, float s,
                                          int mask, unsigned lam) {
    const u64 c2 = bc2(c);
    const u64 sg2 = bc2(lam ? s : -s);
#pragma unroll
    for (int r = 0; r < 8; r++) {
        u64 p = shflx2(a[r], mask);
        a[r] = fma2(sg2, p, mul2(c2, a[r]));
    }
}

__device__ __forceinline__ void ry_reg_m(u64 (&a)[8], float c, float s, int m) {
    const u64 c2 = bc2(c), s2 = bc2(s), ns2 = bc2(-s);
#pragma unroll
    for (int r = 0; r < 8; r++) {
        if (!(r & m)) {
            u64 x = a[r], y = a[r | m];
            a[r]     = fma2(ns2, y, mul2(c2, x));
            a[r | m] = fma2(s2,  x, mul2(c2, y));
        }
    }
}

__device__ __forceinline__ float lane_wht(float v, unsigned lane) {
#pragma unroll
    for (int m = 1; m < 32; m <<= 1) {
        float t = __shfl_xor_sync(0xffffffffu, v, m);
        v = (lane & m) ? (t - v) : (v + t);
    }
    return v;
}

// ---------------- single fused kernel ----------------

__global__ void __launch_bounds__(THREADS, 8)
vqc_kernel(const float4* __restrict__ theta4, const float4* __restrict__ phi4,
           const float4* __restrict__ jup4, const float* __restrict__ w,
           float* __restrict__ out) {
    // block-shared batch-independent tables
    __shared__ float2 s_cs[2 * NQ];      // cos/sin(theta_w/2) per (layer,qubit)
    __shared__ float2 s_hw[NQ];          // (0.5*phi_w(l0), 0.5*phi_w(l1)-0.25*phi_w(l0))
    __shared__ u64    s_d2t[8][32];      // DIAG2 complex factor, transposed [r][lane]

    const unsigned t    = threadIdx.x;
    const unsigned tid  = blockIdx.x * THREADS + t;
    const unsigned b    = tid >> 5;
    const unsigned lane = tid & 31;

    // ---- cooperative table build (w loads are warp-uniform, L1/L2 cached) ----
    if (t < 2 * NQ) {
        float c, s;
        __sincosf(0.5f * w[t * 3 + 1], &s, &c);
        s_cs[t] = make_float2(c, s);
    } else if (t < 3 * NQ) {
        int i = t - 2 * NQ;
        float w0p = w[i * 3], w1p = w[(NQ + i) * 3];
        s_hw[i] = make_float2(0.5f * w0p, fmaf(-0.25f, w0p, 0.5f * w1p));
    }
    {
        int idx = (int)t * 2;            // even entry; odd differs only in r bit0
        int ln = idx >> 3, r0 = idx & 7;
        float h[8];
#pragma unroll
        for (int k = 0; k < 8; k++) h[k] = 0.5f * w[k * 3 + 2];
        float phr = 0.f;
#pragma unroll
        for (int k = 0; k < 5; k++)
            phr += ((ln >> (4 - k)) & 1) ? h[k] : -h[k];
        phr += ((r0 >> 2) & 1) ? h[5] : -h[5];
        phr += ((r0 >> 1) & 1) ? h[6] : -h[6];
        phr -= h[7];                      // r0 bit0 == 0
        float ss, cc;
        __sincosf(phr, &ss, &cc);
        s_d2t[r0][ln] = pk(cc, ss);
        __sincosf(phr + 2.f * h[7], &ss, &cc);
        s_d2t[r0 + 1][ln] = pk(cc, ss);
    }
    __syncthreads();

    // ---- vectorized warp-uniform input loads ----
    float th[NQ], phv[NQ], J[NPAIRS];
    {
        float4 t0 = theta4[b * 2], t1 = theta4[b * 2 + 1];
        th[0]=t0.x; th[1]=t0.y; th[2]=t0.z; th[3]=t0.w;
        th[4]=t1.x; th[5]=t1.y; th[6]=t1.z; th[7]=t1.w;
        float4 p0 = phi4[b * 2], p1 = phi4[b * 2 + 1];
        phv[0]=p0.x; phv[1]=p0.y; phv[2]=p0.z; phv[3]=p0.w;
        phv[4]=p1.x; phv[5]=p1.y; phv[6]=p1.z; phv[7]=p1.w;
#pragma unroll
        for (int q = 0; q < 7; q++) {
            float4 jv = jup4[b * 7 + q];
            J[q*4+0]=jv.x; J[q*4+1]=jv.y; J[q*4+2]=jv.z; J[q*4+3]=jv.w;
        }
    }

    float hc1[NQ];          // 0.5*phi + 0.5*phi_w(l0)
    float cq[NQ], sq[NQ];   // cos/sin(theta/4)
    float ch[NQ], sh[NQ];   // cos/sin(theta/2) via double-angle
#pragma unroll
    for (int k = 0; k < NQ; k++) {
        hc1[k] = fmaf(0.5f, phv[k], s_hw[k].x);
        __sincosf(0.25f * th[k], &sq[k], &cq[k]);
        sh[k] = 2.f * sq[k] * cq[k];
        ch[k] = fmaf(-2.f * sq[k], sq[k], 1.f);
    }

    // ===== Ising Walsh table over reg bits (lane part in index 0) =====
    float exr[8];
    {
        const float HP = 1.5707963267948966f;
        float sg[5];
#pragma unroll
        for (int k = 0; k < 5; k++)
            sg[k] = ((lane >> (4 - k)) & 1) ? 1.f : -1.f;
        float il = 0.f;
        {
            const int PI[10] = {0,0,0,0, 1,1,1, 2,2, 3};
            const int PJ[10] = {1,2,3,4, 2,3,4, 3,4, 4};
            const int PP[10] = {0,1,2,3, 7,8,9, 13,14, 18};
#pragma unroll
            for (int q = 0; q < 10; q++)
                il = fmaf(-sg[PI[q]] * sg[PJ[q]], J[PP[q]], il);
        }
        float U0 = 0.f, U1 = 0.f, U2 = 0.f;
        {
            const int P5[5] = {4, 10, 15, 19, 22};
#pragma unroll
            for (int i = 0; i < 5; i++) {
                U0 = fmaf(sg[i], J[P5[i]],     U0);
                U1 = fmaf(sg[i], J[P5[i] + 1], U1);
                U2 = fmaf(sg[i], J[P5[i] + 2], U2);
            }
        }
        float J56 = J[25], J57 = J[26], J67 = J[27];
        exr[0] = il * HP;  exr[1] = U2 * HP;   exr[2] = U1 * HP;  exr[3] = -J67 * HP;
        exr[4] = U0 * HP;  exr[5] = -J57 * HP; exr[6] = -J56 * HP; exr[7] = 0.f;
    }

    // ===== Fused: product state after encoding RY + DIAG1 phase =====
    u64 a[8];
    {
        float base = 0.f;
#pragma unroll
        for (int k = 0; k < 5; k++)
            base += ((lane >> (4 - k)) & 1) ? hc1[k] : -hc1[k];
        float w0[8];
        w0[0] = base + exr[0];   w0[1] = exr[1] - hc1[7];
        w0[2] = exr[2] - hc1[6]; w0[3] = exr[3];
        w0[4] = exr[4] - hc1[5]; w0[5] = exr[5];
        w0[6] = exr[6];          w0[7] = exr[7];
#pragma unroll
        for (int st = 1; st < 8; st <<= 1) {
#pragma unroll
            for (int i = 0; i < 8; i++) {
                if (!(i & st)) {
                    float u = w0[i], v = w0[i | st];
                    w0[i] = u + v; w0[i | st] = u - v;
                }
            }
        }
        float lf = 1.f;
#pragma unroll
        for (int k = 0; k < 5; k++)
            lf *= ((lane >> (4 - k)) & 1) ? sh[k] : ch[k];
        float f56[4];
        f56[0] = ch[5] * ch[6]; f56[1] = ch[5] * sh[6];
        f56[2] = sh[5] * ch[6]; f56[3] = sh[5] * sh[6];
#pragma unroll
        for (int r = 0; r < 8; r++) {
            float v = lf * f56[r >> 1] * ((r & 1) ? sh[7] : ch[7]);
            float phr = w0[r];
            float q = rintf(phr * 0.15915494309189535f);
            phr = fmaf(q, -6.2831855f, phr);
            float cc, ss;
            __sincosf(phr, &ss, &cc);
            a[r] = pk(v * cc, v * ss);
        }
    }

    // ===== Round A: layer 0 Rot-RY =====
    {
        ry_lane_m(a, s_cs[0].x, s_cs[0].y, 16, (lane >> 4) & 1u);
        ry_lane_m(a, s_cs[1].x, s_cs[1].y,  8, (lane >> 3) & 1u);
        ry_lane_m(a, s_cs[2].x, s_cs[2].y,  4, (lane >> 2) & 1u);
        ry_lane_m(a, s_cs[3].x, s_cs[3].y,  2, (lane >> 1) & 1u);
        ry_lane_m(a, s_cs[4].x, s_cs[4].y,  1,  lane       & 1u);
        ry_reg_m(a, s_cs[5].x, s_cs[5].y, 4);
        ry_reg_m(a, s_cs[6].x, s_cs[6].y, 2);
        ry_reg_m(a, s_cs[7].x, s_cs[7].y, 1);
    }

    // ===== DIAG2 via block-shared complex table (conflict-free LDS.64) =====
#pragma unroll
    for (int r = 0; r < 8; r++) {
        u64 v = s_d2t[r][lane];
        float cc, ss, x, y;
        upk(v, cc, ss); upk(a[r], x, y);
        a[r] = pk(fmaf(cc, x, -ss * y), fmaf(cc, y, ss * x));
    }

    // ===== CNOT ring 1: lane part folded into relabeling =====
    const unsigned lam4 = (lane >> 4) & 1u;
    const unsigned lam3 = lam4 ^ ((lane >> 3) & 1u);
    const unsigned lam2 = lam3 ^ ((lane >> 2) & 1u);
    const unsigned lam1 = lam2 ^ ((lane >> 1) & 1u);
    const unsigned lam0 = lam1 ^ (lane & 1u);

    {
        const bool cs = lam0;
#pragma unroll
        for (int r = 0; r < 4; r++) {
            u64 t0 = a[r], t1 = a[r | 4];
            a[r]     = cs ? t1 : t0;
            a[r | 4] = cs ? t0 : t1;
        }
    }
    { u64 q = a[4]; a[4] = a[6]; a[6] = q; q = a[5]; a[5] = a[7]; a[7] = q; }
    { u64 q = a[2]; a[2] = a[3]; a[3] = q; q = a[6]; a[6] = a[7]; a[7] = q; }
#pragma unroll
    for (int r = 1; r < 8; r += 2) a[r] = shflx2(a[r], 24);

    // ===== Round B: per-qubit U = RY(psi1) * RZ(2*hc3) * RY(theta/2-enc) =====
    {
        const int  MSK[5]  = { 24, 12, 6, 3, 1 };
        const unsigned LAMV[5] = { lam4, lam3, lam2, lam1, lam0 };
#pragma unroll
        for (int k = 0; k < NQ; k++) {
            float hc3 = fmaf(0.5f, hc1[k], s_hw[k].y);
            float cd, sd;
            __sincosf(hc3, &sd, &cd);
            float2 pw = s_cs[NQ + k];               // cos/sin(psi1/2)
            float t1 = pw.x * cq[k], t2 = pw.y * sq[k];
            float t3 = pw.x * sq[k], t4 = pw.y * cq[k];
            float P = t1 - t2, Q = t1 + t2, R = t3 + t4, S = t4 - t3;
            float cdP = cd * P, sdQ = sd * Q, cdR = cd * R, sdS = sd * S;
            if (k < 5) {
                const unsigned bb = LAMV[k];
                const float csy = bb ? sdQ : -sdQ;
                const float cpx = bb ? cdR : -cdR;
                const u64 A0 = bc2(cdP), A1 = pk(-csy, csy);
                const u64 B0 = bc2(cpx), B1 = pk(sdS, -sdS);
#pragma unroll
                for (int r = 0; r < 8; r++) {
                    u64 p = shflx2(a[r], MSK[k]);
                    a[r] = fma2(B1, sw2(p),
                           fma2(B0, p,
                           fma2(A1, sw2(a[r]), mul2(A0, a[r]))));
                }
            } else {
                const int m = 1 << (7 - k);
                const u64 C0 = bc2(cdP);
                const u64 Cl = pk(sdQ, -sdQ), Ch = pk(-sdQ, sdQ);
                const u64 D0n = bc2(-cdR), D0p = bc2(cdR);
                const u64 D1 = pk(sdS, -sdS);
#pragma unroll
                for (int r = 0; r < 8; r++) {
                    if (!(r & m)) {
                        u64 lo = a[r], hi = a[r | m];
                        u64 swl = sw2(lo), swh = sw2(hi);
                        a[r]     = fma2(D1, swh, fma2(D0n, hi,
                                   fma2(Cl, swl, mul2(C0, lo))));
                        a[r | m] = fma2(Ch, swh, fma2(C0, hi,
                                   fma2(D1, swl, mul2(D0p, lo))));
                    }
                }
            }
        }
    }

    // DIAG4 deleted (diagonal before permutation+measurement = no-op).
    // CNOT ring 2 folded into measurement characters.

    // ===== expectations: <Z_k>_final = <chi_{M_k}>_pre-ring2 =====
    float pwv[8];
#pragma unroll
    for (int r = 0; r < 8; r++) {
        float x, y; upk(a[r], x, y);
        pwv[r] = fmaf(x, x, y * y);
    }
#pragma unroll
    for (int st = 1; st < 8; st <<= 1) {
#pragma unroll
        for (int i = 0; i < 8; i++) {
            if (!(i & st)) {
                float u = pwv[i], v = pwv[i | st];
                pwv[i] = u + v; pwv[i | st] = u - v;
            }
        }
    }
    float v0 = lane_wht(pwv[0], lane);
    float v2 = lane_wht(pwv[2], lane);
    float v4 = lane_wht(pwv[4], lane);
    float v5 = lane_wht(pwv[5], lane);

    float* ob = out + (size_t)b * NQ;
    if (lane == 3)  ob[0] = v2;
    if (lane == 30) ob[1] = v5;
    if (lane == 12) ob[2] = v0;
    if (lane == 6)  { ob[3] = v0; ob[5] = v4; ob[7] = v5; }
    if (lane == 19) { ob[4] = v0; ob[6] = v2; }
}

extern "C" void kernel_launch(void* const* d_in, const int* in_sizes, int n_in,
                              void* d_out, int out_size) {
    const float4* theta4 = (const float4*)d_in[0];
    const float4* phi4   = (const float4*)d_in[1];
    const float4* jup4   = (const float4*)d_in[2];
    const float*  w      = (const float*)d_in[3];
    float* out = (float*)d_out;

    const int grid = (NB * 32) / THREADS;
    vqc_kernel<<<grid, THREADS>>>(theta4, phi4, jup4, w, out);
}